// round 3
// baseline (speedup 1.0000x reference)
#include <cuda_runtime.h>
#include <cstdint>

#define SS 160
#define LL 128
#define DD 256
#define KK 16

#define THREADS 256
#define PAIRS 4                   // row streams per block (each = 2 warps, one per d-half)
#define B_PER_BLOCK 64
#define ITERS 16                  // rows per stream
#define NBLOCKS (LL * (2048 / B_PER_BLOCK))   // 4096
#define NSLOTS 4

typedef unsigned long long u64;

__device__ float2 g_stats[65536];   // (mu, rsqrt(var+eps)) per 16-bit mask pattern

// ---------------- precompute: LN stats for every mask pattern ----------------
__global__ void precompute_stats(const float* __restrict__ mlp_w,
                                 const float* __restrict__ mlp_b)
{
    __shared__ float G2[16][16];   // 2 * W W^T
    __shared__ float sv[16];       // row sums of W
    __shared__ float d2c[16];      // G_kk + 2 c_k   (c = W b)
    __shared__ float sbb[2];       // sum(b), sum(b^2)

    const int tid = threadIdx.x;
    const int k = tid >> 4, j = tid & 15;

    float acc = 0.f;
    for (int d = 0; d < DD; d += 4) {
        float4 a = *(const float4*)(mlp_w + k * DD + d);
        float4 b = *(const float4*)(mlp_w + j * DD + d);
        acc = fmaf(a.x, b.x, fmaf(a.y, b.y, fmaf(a.z, b.z, fmaf(a.w, b.w, acc))));
    }
    G2[k][j] = 2.0f * acc;
    if (k == j) {
        float c = 0.f, s = 0.f;
        for (int d = 0; d < DD; d += 4) {
            float4 a = *(const float4*)(mlp_w + k * DD + d);
            float4 b = *(const float4*)(mlp_b + d);
            c = fmaf(a.x, b.x, fmaf(a.y, b.y, fmaf(a.z, b.z, fmaf(a.w, b.w, c))));
            s += (a.x + a.y) + (a.z + a.w);
        }
        d2c[k] = fmaf(2.f, c, acc);    // acc == G_kk here
        sv[k]  = s;
    }
    if (tid == 0) {
        float sb = 0.f, bb = 0.f;
        for (int d = 0; d < DD; d++) { float b = mlp_b[d]; sb += b; bb = fmaf(b, b, bb); }
        sbb[0] = sb; sbb[1] = bb;
    }
    __syncthreads();

    const int p = blockIdx.x * 256 + tid;
    float sum = sbb[0], ss = sbb[1];
#pragma unroll
    for (int kk = 0; kk < 16; kk++) {
        if ((p >> kk) & 1) {
            sum += sv[kk];
            ss  += d2c[kk];
#pragma unroll
            for (int jj = 0; jj < kk; jj++)
                if ((p >> jj) & 1) ss += G2[kk][jj];
        }
    }
    const float mu  = sum * (1.0f / DD);
    const float var = fmaf(-mu, mu, ss * (1.0f / DD));
    float2 r; r.x = mu; r.y = rsqrtf(var + 1e-5f);
    g_stats[p] = r;
}

// ---------------- main kernel ----------------
struct __align__(16) Slot {
    float m[KK];     // 64 B masks
    int4  ids;       // x=tok, y=actor, z=street
};

__device__ __forceinline__ uint32_t saddr(const void* p) {
    return (uint32_t)__cvta_generic_to_shared(p);
}
__device__ __forceinline__ void cp16(uint32_t s, const void* g) {
    asm volatile("cp.async.cg.shared.global [%0], [%1], 16;" :: "r"(s), "l"(g));
}
__device__ __forceinline__ void cp4(uint32_t s, const void* g) {
    asm volatile("cp.async.ca.shared.global [%0], [%1], 4;" :: "r"(s), "l"(g));
}
#define CP_COMMIT() asm volatile("cp.async.commit_group;" ::: "memory")
#define CP_WAIT1()  asm volatile("cp.async.wait_group 1;" ::: "memory")

__device__ __forceinline__ u64 pack2(float lo, float hi) {
    u64 r; asm("mov.b64 %0, {%1, %2};" : "=l"(r) : "f"(lo), "f"(hi)); return r;
}
__device__ __forceinline__ void unpack2(float& lo, float& hi, u64 v) {
    asm("mov.b64 {%0, %1}, %2;" : "=f"(lo), "=f"(hi) : "l"(v));
}
__device__ __forceinline__ u64 fma2(u64 a, u64 b, u64 c) {
    u64 d; asm("fma.rn.f32x2 %0, %1, %2, %3;" : "=l"(d) : "l"(a), "l"(b), "l"(c)); return d;
}

__global__ __launch_bounds__(THREADS, 2)
void action_emb_kernel(const int*   __restrict__ token_ids,
                       const int*   __restrict__ actors,
                       const int*   __restrict__ streets,
                       const float* __restrict__ masks,
                       const float* __restrict__ actor_w,
                       const float* __restrict__ street_w,
                       const float* __restrict__ pos_w,
                       const float* __restrict__ mlp_w,
                       const float* __restrict__ mlp_b,
                       const float* __restrict__ ln_g,
                       const float* __restrict__ ln_b,
                       float*       __restrict__ out)
{
    const int tid  = threadIdx.x;
    const int lane = tid & 31;
    const int warp = tid >> 5;      // 0..7
    const int pair = warp >> 1;     // row stream 0..3
    const int half = warp & 1;      // which 128-dim half
    const int d0   = half * 128 + lane * 4;

    const int l     = blockIdx.x & (LL - 1);
    const int chunk = blockIdx.x >> 7;
    const int b0    = chunk * B_PER_BLOCK + pair;

    __shared__ Slot slots[NSLOTS][8];

    // ---- per-thread constants ----
    u64 wA[KK], wB[KK];
#pragma unroll
    for (int k = 0; k < KK; k++) {
        float4 w = *(const float4*)(mlp_w + k * DD + d0);
        wA[k] = pack2(w.x, w.y);
        wB[k] = pack2(w.z, w.w);
    }
    const float4 bias = *(const float4*)(mlp_b + d0);
    const u64 bA = pack2(bias.x, bias.y);
    const u64 bB = pack2(bias.z, bias.w);
    const float4 gn  = *(const float4*)(ln_g + d0);
    const float4 bn  = *(const float4*)(ln_b + d0);
    const float4 pos = *(const float4*)(pos_w + l * DD + d0);

    int oofs = (b0 * LL + l) * DD + d0;
    const int OSTEP = PAIRS * LL * DD;

    auto issue = [&](int it2) {
        if (it2 < ITERS) {
            const int b = b0 + it2 * PAIRS;
            const long idc = (long)b * SS + l;
            Slot* sl = &slots[it2 & (NSLOTS - 1)][warp];
            if (lane < 4)       cp16(saddr(&sl->m[lane * 4]), masks + idc * KK + lane * 4);
            else if (lane == 4) cp4(saddr(&sl->ids.x), token_ids + idc);
            else if (lane == 5) cp4(saddr(&sl->ids.y), actors + idc);
            else if (lane == 6) cp4(saddr(&sl->ids.z), streets + idc);
        }
        CP_COMMIT();
    };

    issue(0);
    issue(1);
    CP_WAIT1();
    __syncwarp();

    // stats prefetch for it = 0
    float2 mr;
    {
        Slot* s0 = &slots[0][warp];
        const float mv = s0->m[lane & 15];
        const unsigned bal =
            __ballot_sync(0xffffffffu, (lane < 16) && (mv != 0.0f));
        mr = __ldg(&g_stats[bal]);
    }

#pragma unroll 1
    for (int it = 0; it < ITERS; it++) {
        Slot* sl = &slots[it & (NSLOTS - 1)][warp];

        const int4 ids = sl->ids;
        const float4 aw = __ldg((const float4*)(actor_w  + ids.y * DD + d0));
        const float4 sw = __ldg((const float4*)(street_w + ids.z * DD + d0));

        const float4 m0 = *(const float4*)&sl->m[0];
        const float4 m1 = *(const float4*)&sl->m[4];
        const float4 m2 = *(const float4*)&sl->m[8];
        const float4 m3 = *(const float4*)&sl->m[12];
        const float mm[KK] = {m0.x, m0.y, m0.z, m0.w,
                              m1.x, m1.y, m1.z, m1.w,
                              m2.x, m2.y, m2.z, m2.w,
                              m3.x, m3.y, m3.z, m3.w};

        // ---- h = masks @ W + b  via packed f32x2 FMA ----
        u64 hA = bA, hB = bB;
#pragma unroll
        for (int k = 0; k < KK; k++) {
            const u64 mk = pack2(mm[k], mm[k]);
            hA = fma2(mk, wA[k], hA);
            hB = fma2(mk, wB[k], hB);
        }

        // ---- keep the prefetch ring rolling ----
        issue(it + 2);
        CP_WAIT1();
        __syncwarp();

        // ---- prefetch LN stats for it+1 (slot it+1 just became visible) ----
        Slot* sn = &slots[(it + 1) & (NSLOTS - 1)][warp];
        const float mvn = sn->m[lane & 15];
        const unsigned baln =
            __ballot_sync(0xffffffffu, (lane < 16) && (mvn != 0.0f));
        const float2 mrN = __ldg(&g_stats[baln]);

        // ---- epilogue ----
        float h0, h1, h2, h3;
        unpack2(h0, h1, hA);
        unpack2(h2, h3, hB);

        const float rs   = mr.y;
        const float nmrs = -mr.x * rs;

        const float ex = aw.x + sw.x + pos.x;
        const float ey = aw.y + sw.y + pos.y;
        const float ez = aw.z + sw.z + pos.z;
        const float ew = aw.w + sw.w + pos.w;

        float4 o;
        o.x = fmaxf(fmaf(fmaf(h0, rs, nmrs), gn.x, bn.x), 0.0f) + ex;
        o.y = fmaxf(fmaf(fmaf(h1, rs, nmrs), gn.y, bn.y), 0.0f) + ey;
        o.z = fmaxf(fmaf(fmaf(h2, rs, nmrs), gn.z, bn.z), 0.0f) + ez;
        o.w = fmaxf(fmaf(fmaf(h3, rs, nmrs), gn.w, bn.w), 0.0f) + ew;

        if (ids.x < 0) { o.x = 0.0f; o.y = 0.0f; o.z = 0.0f; o.w = 0.0f; }

        *(float4*)(out + oofs) = o;
        oofs += OSTEP;
        mr = mrN;
    }
}

extern "C" void kernel_launch(void* const* d_in, const int* in_sizes, int n_in,
                              void* d_out, int out_size)
{
    const int*   token_ids = (const int*)  d_in[0];
    const int*   actors    = (const int*)  d_in[1];
    const int*   streets   = (const int*)  d_in[2];
    const float* masks     = (const float*)d_in[3];
    const float* actor_w   = (const float*)d_in[4];
    const float* street_w  = (const float*)d_in[5];
    const float* pos_w     = (const float*)d_in[6];
    const float* mlp_w     = (const float*)d_in[7];
    const float* mlp_b     = (const float*)d_in[8];
    const float* ln_g      = (const float*)d_in[9];
    const float* ln_b      = (const float*)d_in[10];
    float*       out       = (float*)d_out;

    precompute_stats<<<256, 256>>>(mlp_w, mlp_b);
    action_emb_kernel<<<NBLOCKS, THREADS>>>(
        token_ids, actors, streets, masks,
        actor_w, street_w, pos_w, mlp_w, mlp_b, ln_g, ln_b, out);
}

// round 4
// speedup vs baseline: 1.3835x; 1.3835x over previous
#include <cuda_runtime.h>
#include <cstdint>

#define SS 160
#define LL 128
#define DD 256
#define KK 16

#define THREADS 256
#define PAIRS 4                   // row streams per block (each = 2 warps)
#define B_PER_BLOCK 64
#define ITERS 16                  // rows per stream
#define NBLOCKS (LL * (2048 / B_PER_BLOCK))   // 4096
#define NSLOTS 4

__device__ float  g_T[4 * 16 * DD];   // nibble tables, bias folded into T0
__device__ float2 g_stats[65536];     // (mu, rsqrt(var+eps)) per mask pattern

// ---------- Kernel A: build nibble tables (trivial) ----------
__global__ void build_tables(const float* __restrict__ mlp_w,
                             const float* __restrict__ mlp_b)
{
    const int d = threadIdx.x;            // 256 threads, one per column
    float w[KK];
#pragma unroll
    for (int k = 0; k < KK; k++) w[k] = mlp_w[k * DD + d];
    const float b = mlp_b[d];
#pragma unroll
    for (int i = 0; i < 4; i++) {
#pragma unroll
        for (int q = 0; q < 16; q++) {
            float acc = (i == 0) ? b : 0.0f;
#pragma unroll
            for (int k = 0; k < 4; k++)
                if ((q >> k) & 1) acc += w[i * 4 + k];
            g_T[(i * 16 + q) * DD + d] = acc;
        }
    }
}

// ---------- Kernel B: LN stats per pattern from composed h ----------
__global__ void build_stats()
{
    const int lane = threadIdx.x & 31;
    const int p    = (blockIdx.x * blockDim.x + threadIdx.x) >> 5;  // warp id
    const int q0 = p & 15, q1 = (p >> 4) & 15, q2 = (p >> 8) & 15, q3 = (p >> 12) & 15;

    float s = 0.f, sq = 0.f;
    int d = lane * 8;
#pragma unroll
    for (int c = 0; c < 2; c++) {
        const float4 a = __ldg((const float4*)&g_T[(      q0) * DD + d]);
        const float4 b = __ldg((const float4*)&g_T[(16 + q1) * DD + d]);
        const float4 e = __ldg((const float4*)&g_T[(32 + q2) * DD + d]);
        const float4 f = __ldg((const float4*)&g_T[(48 + q3) * DD + d]);
        const float h0 = (a.x + b.x) + (e.x + f.x);
        const float h1 = (a.y + b.y) + (e.y + f.y);
        const float h2 = (a.z + b.z) + (e.z + f.z);
        const float h3 = (a.w + b.w) + (e.w + f.w);
        s  += (h0 + h1) + (h2 + h3);
        sq  = fmaf(h0, h0, fmaf(h1, h1, fmaf(h2, h2, fmaf(h3, h3, sq))));
        d += 4;
    }
#pragma unroll
    for (int o = 16; o > 0; o >>= 1) {
        s  += __shfl_xor_sync(0xffffffffu, s,  o);
        sq += __shfl_xor_sync(0xffffffffu, sq, o);
    }
    if (lane == 0) {
        const float mu  = s * (1.0f / DD);
        const float var = fmaf(-mu, mu, sq * (1.0f / DD));
        float2 r; r.x = mu; r.y = rsqrtf(var + 1e-5f);
        g_stats[p] = r;
    }
}

// ---------- main kernel ----------
struct __align__(16) Slot {
    float m[KK];     // 64 B masks
    int4  ids;       // x=tok, y=actor, z=street
};

__device__ __forceinline__ uint32_t saddr(const void* p) {
    return (uint32_t)__cvta_generic_to_shared(p);
}
__device__ __forceinline__ void cp16(uint32_t s, const void* g) {
    asm volatile("cp.async.cg.shared.global [%0], [%1], 16;" :: "r"(s), "l"(g));
}
__device__ __forceinline__ void cp4(uint32_t s, const void* g) {
    asm volatile("cp.async.ca.shared.global [%0], [%1], 4;" :: "r"(s), "l"(g));
}
#define CP_COMMIT() asm volatile("cp.async.commit_group;" ::: "memory")
#define CP_WAIT1()  asm volatile("cp.async.wait_group 1;" ::: "memory")

__global__ __launch_bounds__(THREADS, 3)
void action_emb_kernel(const int*   __restrict__ token_ids,
                       const int*   __restrict__ actors,
                       const int*   __restrict__ streets,
                       const float* __restrict__ masks,
                       const float* __restrict__ actor_w,
                       const float* __restrict__ street_w,
                       const float* __restrict__ pos_w,
                       const float* __restrict__ ln_g,
                       const float* __restrict__ ln_b,
                       float*       __restrict__ out)
{
    const int tid  = threadIdx.x;
    const int lane = tid & 31;
    const int warp = tid >> 5;      // 0..7
    const int pair = warp >> 1;     // row stream 0..3
    const int half = warp & 1;      // which 128-dim half
    const int d0   = half * 128 + lane * 4;

    const int l     = blockIdx.x & (LL - 1);
    const int chunk = blockIdx.x >> 7;
    const int b0    = chunk * B_PER_BLOCK + pair;

    __shared__ Slot slots[NSLOTS][8];

    // per-thread constants
    const float4 gn  = *(const float4*)(ln_g + d0);
    const float4 bn  = *(const float4*)(ln_b + d0);
    const float4 pos = *(const float4*)(pos_w + l * DD + d0);

    int oofs = (b0 * LL + l) * DD + d0;
    const int OSTEP = PAIRS * LL * DD;

    auto issue = [&](int it2) {
        if (it2 < ITERS) {
            const int  b   = b0 + it2 * PAIRS;
            const long idc = (long)b * SS + l;
            Slot* sl = &slots[it2 & (NSLOTS - 1)][warp];
            if (lane < 4)       cp16(saddr(&sl->m[lane * 4]), masks + idc * KK + lane * 4);
            else if (lane == 4) cp4(saddr(&sl->ids.x), token_ids + idc);
            else if (lane == 5) cp4(saddr(&sl->ids.y), actors + idc);
            else if (lane == 6) cp4(saddr(&sl->ids.z), streets + idc);
        }
        CP_COMMIT();
    };

    issue(0);
    issue(1);
    CP_WAIT1();
    __syncwarp();

    // pattern + stats prefetch for it = 0
    unsigned pat;
    float2 mr;
    {
        Slot* s0 = &slots[0][warp];
        const float mv = s0->m[lane & 15];
        pat = __ballot_sync(0xffffffffu, (lane < 16) && (mv != 0.0f));
        mr  = __ldg(&g_stats[pat]);
    }

#pragma unroll 1
    for (int it = 0; it < ITERS; it++) {
        Slot* sl = &slots[it & (NSLOTS - 1)][warp];

        const int4 ids = sl->ids;
        const float4 aw = __ldg((const float4*)(actor_w  + ids.y * DD + d0));
        const float4 sw = __ldg((const float4*)(street_w + ids.z * DD + d0));

        // ---- h from nibble tables (L1-resident) ----
        const unsigned q0 =  pat        & 15u;
        const unsigned q1 = (pat >>  4) & 15u;
        const unsigned q2 = (pat >>  8) & 15u;
        const unsigned q3 = (pat >> 12) & 15u;
        const float4 t0 = __ldg((const float4*)&g_T[(      q0) * DD + d0]);
        const float4 t1 = __ldg((const float4*)&g_T[(16 + q1) * DD + d0]);
        const float4 t2 = __ldg((const float4*)&g_T[(32 + q2) * DD + d0]);
        const float4 t3 = __ldg((const float4*)&g_T[(48 + q3) * DD + d0]);

        const float h0 = (t0.x + t1.x) + (t2.x + t3.x);
        const float h1 = (t0.y + t1.y) + (t2.y + t3.y);
        const float h2 = (t0.z + t1.z) + (t2.z + t3.z);
        const float h3 = (t0.w + t1.w) + (t2.w + t3.w);

        // ---- keep prefetch ring rolling ----
        issue(it + 2);
        CP_WAIT1();
        __syncwarp();

        // ---- prefetch next iteration's pattern + stats ----
        Slot* sn = &slots[(it + 1) & (NSLOTS - 1)][warp];
        const float mvn = sn->m[lane & 15];
        const unsigned patN =
            __ballot_sync(0xffffffffu, (lane < 16) && (mvn != 0.0f));
        const float2 mrN = __ldg(&g_stats[patN]);

        // ---- epilogue ----
        const float rs   = mr.y;
        const float nmrs = -mr.x * rs;

        const float ex = aw.x + sw.x + pos.x;
        const float ey = aw.y + sw.y + pos.y;
        const float ez = aw.z + sw.z + pos.z;
        const float ew = aw.w + sw.w + pos.w;

        float4 o;
        o.x = fmaxf(fmaf(fmaf(h0, rs, nmrs), gn.x, bn.x), 0.0f) + ex;
        o.y = fmaxf(fmaf(fmaf(h1, rs, nmrs), gn.y, bn.y), 0.0f) + ey;
        o.z = fmaxf(fmaf(fmaf(h2, rs, nmrs), gn.z, bn.z), 0.0f) + ez;
        o.w = fmaxf(fmaf(fmaf(h3, rs, nmrs), gn.w, bn.w), 0.0f) + ew;

        if (ids.x < 0) { o.x = 0.0f; o.y = 0.0f; o.z = 0.0f; o.w = 0.0f; }

        *(float4*)(out + oofs) = o;
        oofs += OSTEP;
        pat = patN;
        mr  = mrN;
    }
}

extern "C" void kernel_launch(void* const* d_in, const int* in_sizes, int n_in,
                              void* d_out, int out_size)
{
    const int*   token_ids = (const int*)  d_in[0];
    const int*   actors    = (const int*)  d_in[1];
    const int*   streets   = (const int*)  d_in[2];
    const float* masks     = (const float*)d_in[3];
    const float* actor_w   = (const float*)d_in[4];
    const float* street_w  = (const float*)d_in[5];
    const float* pos_w     = (const float*)d_in[6];
    const float* mlp_w     = (const float*)d_in[7];
    const float* mlp_b     = (const float*)d_in[8];
    const float* ln_g      = (const float*)d_in[9];
    const float* ln_b      = (const float*)d_in[10];
    float*       out       = (float*)d_out;

    build_tables<<<1, 256>>>(mlp_w, mlp_b);
    build_stats<<<8192, 256>>>();
    action_emb_kernel<<<NBLOCKS, THREADS>>>(
        token_ids, actors, streets, masks,
        actor_w, street_w, pos_w, ln_g, ln_b, out);
}

// round 5
// speedup vs baseline: 1.4674x; 1.0607x over previous
#include <cuda_runtime.h>
#include <cstdint>

#define SS 160
#define LL 128
#define DD 256
#define KK 16

#define THREADS 256
#define WARPS 8                     // row streams per block (one warp each)
#define B_PER_BLOCK 64
#define ITERS (B_PER_BLOCK / WARPS)           // 8
#define NBLOCKS (LL * (2048 / B_PER_BLOCK))   // 4096
#define NSLOTS 4

__device__ float  g_T[64 * DD];          // nibble tables, bias folded into T0
__device__ float  g_combo[LL * 8 * DD];  // pos + actor + street, per (l, a*4+s)
__device__ float  g_S[64], g_Q[64];      // per-nibble-entry sum / sumsq
__device__ float  g_D[6 * 256];          // pairwise dot tables
__device__ float2 g_stats[65536];        // (mu, rsqrt(var+eps)) per pattern

// ---------- K1: nibble tables + combo embeddings ----------
__global__ void precompute1(const float* __restrict__ mlp_w,
                            const float* __restrict__ mlp_b,
                            const float* __restrict__ actor_w,
                            const float* __restrict__ street_w,
                            const float* __restrict__ pos_w)
{
    const int d   = threadIdx.x;
    const int bid = blockIdx.x;
    if (bid < 64) {
        const int i = bid >> 4, q = bid & 15;
        float acc = (i == 0) ? mlp_b[d] : 0.0f;
#pragma unroll
        for (int k = 0; k < 4; k++)
            if ((q >> k) & 1) acc += mlp_w[(i * 4 + k) * DD + d];
        g_T[bid * DD + d] = acc;
    } else {
        const int cb = bid - 64;           // l*8 + (a*4+s)
        const int c  = cb & 7;
        const int l  = cb >> 3;
        const int a  = c >> 2, s = c & 3;
        g_combo[cb * DD + d] =
            actor_w[a * DD + d] + street_w[s * DD + d] + pos_w[l * DD + d];
    }
}

// ---------- K2: per-nibble sums/sumsqs + pairwise dot tables ----------
__global__ void precompute2()
{
    const int lane = threadIdx.x;   // 32 threads
    const int bid  = blockIdx.x;
    const int d    = lane * 8;

    if (bid < 1536) {
        const int pair = bid >> 8;
        const int e    = bid & 255;
        const int qi   = e >> 4, qj = e & 15;
        const int pi[6] = {0, 0, 0, 1, 1, 2};
        const int pj[6] = {1, 2, 3, 2, 3, 3};
        const float* ti = g_T + (pi[pair] * 16 + qi) * DD + d;
        const float* tj = g_T + (pj[pair] * 16 + qj) * DD + d;
        const float4 a0 = *(const float4*)ti;
        const float4 a1 = *(const float4*)(ti + 4);
        const float4 b0 = *(const float4*)tj;
        const float4 b1 = *(const float4*)(tj + 4);
        float acc = a0.x*b0.x + a0.y*b0.y + a0.z*b0.z + a0.w*b0.w
                  + a1.x*b1.x + a1.y*b1.y + a1.z*b1.z + a1.w*b1.w;
#pragma unroll
        for (int o = 16; o > 0; o >>= 1)
            acc += __shfl_xor_sync(0xffffffffu, acc, o);
        if (lane == 0) g_D[pair * 256 + e] = acc;
    } else {
        const int s = bid - 1536;          // 0..63
        const float* t = g_T + s * DD + d;
        const float4 a0 = *(const float4*)t;
        const float4 a1 = *(const float4*)(t + 4);
        float sum = (a0.x + a0.y) + (a0.z + a0.w)
                  + (a1.x + a1.y) + (a1.z + a1.w);
        float sq  = a0.x*a0.x + a0.y*a0.y + a0.z*a0.z + a0.w*a0.w
                  + a1.x*a1.x + a1.y*a1.y + a1.z*a1.z + a1.w*a1.w;
#pragma unroll
        for (int o = 16; o > 0; o >>= 1) {
            sum += __shfl_xor_sync(0xffffffffu, sum, o);
            sq  += __shfl_xor_sync(0xffffffffu, sq,  o);
        }
        if (lane == 0) { g_S[s] = sum; g_Q[s] = sq; }
    }
}

// ---------- K3: LN stats per 16-bit pattern (pure table math) ----------
__global__ void precompute3()
{
    const int p  = blockIdx.x * 256 + threadIdx.x;
    const int q0 = p & 15, q1 = (p >> 4) & 15, q2 = (p >> 8) & 15, q3 = p >> 12;
    const float sum = g_S[q0] + g_S[16 + q1] + g_S[32 + q2] + g_S[48 + q3];
    const float sq  = g_Q[q0] + g_Q[16 + q1] + g_Q[32 + q2] + g_Q[48 + q3]
        + 2.0f * ( g_D[0*256 + q0*16 + q1] + g_D[1*256 + q0*16 + q2]
                 + g_D[2*256 + q0*16 + q3] + g_D[3*256 + q1*16 + q2]
                 + g_D[4*256 + q1*16 + q3] + g_D[5*256 + q2*16 + q3]);
    const float mu  = sum * (1.0f / DD);
    const float var = fmaf(-mu, mu, sq * (1.0f / DD));
    float2 r; r.x = mu; r.y = rsqrtf(var + 1e-5f);
    g_stats[p] = r;
}

// ---------- main kernel ----------
struct __align__(16) Slot {
    float m[KK];     // 64 B masks
    int4  ids;       // x=tok, y=actor, z=street
};

__device__ __forceinline__ uint32_t saddr(const void* p) {
    return (uint32_t)__cvta_generic_to_shared(p);
}
__device__ __forceinline__ void cp16(uint32_t s, const void* g) {
    asm volatile("cp.async.cg.shared.global [%0], [%1], 16;" :: "r"(s), "l"(g));
}
__device__ __forceinline__ void cp4(uint32_t s, const void* g) {
    asm volatile("cp.async.ca.shared.global [%0], [%1], 4;" :: "r"(s), "l"(g));
}
#define CP_COMMIT() asm volatile("cp.async.commit_group;" ::: "memory")
#define CP_WAIT2()  asm volatile("cp.async.wait_group 2;" ::: "memory")

__global__ __launch_bounds__(THREADS, 3)
void action_emb_kernel(const int*   __restrict__ token_ids,
                       const int*   __restrict__ actors,
                       const int*   __restrict__ streets,
                       const float* __restrict__ masks,
                       const float* __restrict__ ln_g,
                       const float* __restrict__ ln_b,
                       float*       __restrict__ out)
{
    const int tid  = threadIdx.x;
    const int lane = tid & 31;
    const int warp = tid >> 5;      // row stream 0..7
    const int d0   = lane * 8;      // 8 owned dims

    const int l     = blockIdx.x & (LL - 1);
    const int chunk = blockIdx.x >> 7;
    const int b0    = chunk * B_PER_BLOCK + warp;

    __shared__ Slot slots[NSLOTS][WARPS];

    // per-thread constants
    const float4 gnA = *(const float4*)(ln_g + d0);
    const float4 gnB = *(const float4*)(ln_g + d0 + 4);
    const float4 bnA = *(const float4*)(ln_b + d0);
    const float4 bnB = *(const float4*)(ln_b + d0 + 4);
    const float* comboL = g_combo + (l * 8) * DD + d0;

    int oofs = (b0 * LL + l) * DD + d0;
    const int OSTEP = WARPS * LL * DD;

    auto issue = [&](int it2) {
        if (it2 < ITERS) {
            const int  b   = b0 + it2 * WARPS;
            const long idc = (long)b * SS + l;
            Slot* sl = &slots[it2 & (NSLOTS - 1)][warp];
            if (lane < 4)       cp16(saddr(&sl->m[lane * 4]), masks + idc * KK + lane * 4);
            else if (lane == 4) cp4(saddr(&sl->ids.x), token_ids + idc);
            else if (lane == 5) cp4(saddr(&sl->ids.y), actors + idc);
            else if (lane == 6) cp4(saddr(&sl->ids.z), streets + idc);
        }
        CP_COMMIT();
    };

    // prologue: fill 3 slots (prefetch distance 3)
    issue(0);
    issue(1);
    issue(2);
    CP_WAIT2();        // slot 0 landed
    __syncwarp();

    // pattern + stats for it = 0
    unsigned pat;
    float2 mr;
    {
        Slot* s0 = &slots[0][warp];
        const float mv = s0->m[lane & 15];
        pat = __ballot_sync(0xffffffffu, (lane < 16) && (mv != 0.0f));
        mr  = __ldg(&g_stats[pat]);
    }

#pragma unroll 1
    for (int it = 0; it < ITERS; it++) {
        Slot* sl = &slots[it & (NSLOTS - 1)][warp];
        const int4 ids = sl->ids;

        // combined actor+street+pos embedding (L1-hot: 8 KB per block)
        const float* cb = comboL + (ids.y * 4 + ids.z) * DD;
        const float4 cA = __ldg((const float4*)cb);
        const float4 cB = __ldg((const float4*)(cb + 4));

        // h from nibble tables
        const unsigned q0 =  pat        & 15u;
        const unsigned q1 = (pat >>  4) & 15u;
        const unsigned q2 = (pat >>  8) & 15u;
        const unsigned q3 =  pat >> 12;
        const float* T0 = g_T + (     q0) * DD + d0;
        const float* T1 = g_T + (16 + q1) * DD + d0;
        const float* T2 = g_T + (32 + q2) * DD + d0;
        const float* T3 = g_T + (48 + q3) * DD + d0;
        const float4 t0A = __ldg((const float4*)T0);
        const float4 t1A = __ldg((const float4*)T1);
        const float4 t2A = __ldg((const float4*)T2);
        const float4 t3A = __ldg((const float4*)T3);
        const float4 t0B = __ldg((const float4*)(T0 + 4));
        const float4 t1B = __ldg((const float4*)(T1 + 4));
        const float4 t2B = __ldg((const float4*)(T2 + 4));
        const float4 t3B = __ldg((const float4*)(T3 + 4));

        const float h0 = (t0A.x + t1A.x) + (t2A.x + t3A.x);
        const float h1 = (t0A.y + t1A.y) + (t2A.y + t3A.y);
        const float h2 = (t0A.z + t1A.z) + (t2A.z + t3A.z);
        const float h3 = (t0A.w + t1A.w) + (t2A.w + t3A.w);
        const float h4 = (t0B.x + t1B.x) + (t2B.x + t3B.x);
        const float h5 = (t0B.y + t1B.y) + (t2B.y + t3B.y);
        const float h6 = (t0B.z + t1B.z) + (t2B.z + t3B.z);
        const float h7 = (t0B.w + t1B.w) + (t2B.w + t3B.w);

        // keep the prefetch ring rolling (distance 3)
        issue(it + 3);
        CP_WAIT2();
        __syncwarp();

        // prefetch next iteration's pattern + stats
        Slot* sn = &slots[(it + 1) & (NSLOTS - 1)][warp];
        const float mvn = sn->m[lane & 15];
        const unsigned patN =
            __ballot_sync(0xffffffffu, (lane < 16) && (mvn != 0.0f));
        const float2 mrN = __ldg(&g_stats[patN]);

        // epilogue: LN affine, relu, + combo, validity
        const float rs   = mr.y;
        const float nmrs = -mr.x * rs;

        float4 oA, oB;
        oA.x = fmaxf(fmaf(fmaf(h0, rs, nmrs), gnA.x, bnA.x), 0.0f) + cA.x;
        oA.y = fmaxf(fmaf(fmaf(h1, rs, nmrs), gnA.y, bnA.y), 0.0f) + cA.y;
        oA.z = fmaxf(fmaf(fmaf(h2, rs, nmrs), gnA.z, bnA.z), 0.0f) + cA.z;
        oA.w = fmaxf(fmaf(fmaf(h3, rs, nmrs), gnA.w, bnA.w), 0.0f) + cA.w;
        oB.x = fmaxf(fmaf(fmaf(h4, rs, nmrs), gnB.x, bnB.x), 0.0f) + cB.x;
        oB.y = fmaxf(fmaf(fmaf(h5, rs, nmrs), gnB.y, bnB.y), 0.0f) + cB.y;
        oB.z = fmaxf(fmaf(fmaf(h6, rs, nmrs), gnB.z, bnB.z), 0.0f) + cB.z;
        oB.w = fmaxf(fmaf(fmaf(h7, rs, nmrs), gnB.w, bnB.w), 0.0f) + cB.w;

        if (ids.x < 0) {
            oA.x = oA.y = oA.z = oA.w = 0.0f;
            oB.x = oB.y = oB.z = oB.w = 0.0f;
        }

        *(float4*)(out + oofs)     = oA;
        *(float4*)(out + oofs + 4) = oB;
        oofs += OSTEP;
        pat = patN;
        mr  = mrN;
    }
}

extern "C" void kernel_launch(void* const* d_in, const int* in_sizes, int n_in,
                              void* d_out, int out_size)
{
    const int*   token_ids = (const int*)  d_in[0];
    const int*   actors    = (const int*)  d_in[1];
    const int*   streets   = (const int*)  d_in[2];
    const float* masks     = (const float*)d_in[3];
    const float* actor_w   = (const float*)d_in[4];
    const float* street_w  = (const float*)d_in[5];
    const float* pos_w     = (const float*)d_in[6];
    const float* mlp_w     = (const float*)d_in[7];
    const float* mlp_b     = (const float*)d_in[8];
    const float* ln_g      = (const float*)d_in[9];
    const float* ln_b      = (const float*)d_in[10];
    float*       out       = (float*)d_out;

    precompute1<<<64 + LL * 8, 256>>>(mlp_w, mlp_b, actor_w, street_w, pos_w);
    precompute2<<<1600, 32>>>();
    precompute3<<<256, 256>>>();
    action_emb_kernel<<<NBLOCKS, THREADS>>>(
        token_ids, actors, streets, masks, ln_g, ln_b, out);
}

// round 6
// speedup vs baseline: 2.0149x; 1.3731x over previous
#include <cuda_runtime.h>
#include <cstdint>

#define SS 160
#define LL 128
#define DD 256
#define KK 16
#define BB 2048

#define THREADS 256
#define WARPS 8
#define B_PER_BLOCK 64
#define ROWS_PER_WARP 8
#define NBLOCKS (LL * (BB / B_PER_BLOCK))   // 4096

__device__ float  g_T[64 * DD];           // nibble tables (for stats math)
__device__ float  g_H[2 * 256 * DD];      // byte tables, bias folded into H0
__device__ float  g_combo[LL * 8 * DD];   // pos + actor + street per (l, a*4+s)
__device__ float  g_S[64], g_Q[64];
__device__ float  g_D[6 * 256];
__device__ float2 g_stats[65536];
__device__ unsigned g_meta[BB * LL];      // pat | a4s<<16 | valid<<31

// ---------- K1: nibble tables + combo + byte tables ----------
__global__ void precompute1(const float* __restrict__ mlp_w,
                            const float* __restrict__ mlp_b,
                            const float* __restrict__ actor_w,
                            const float* __restrict__ street_w,
                            const float* __restrict__ pos_w)
{
    const int d   = threadIdx.x;
    const int bid = blockIdx.x;
    if (bid < 64) {
        const int i = bid >> 4, q = bid & 15;
        float acc = (i == 0) ? mlp_b[d] : 0.0f;
#pragma unroll
        for (int k = 0; k < 4; k++)
            if ((q >> k) & 1) acc += mlp_w[(i * 4 + k) * DD + d];
        g_T[bid * DD + d] = acc;
    } else if (bid < 64 + LL * 8) {
        const int cb = bid - 64;
        const int c  = cb & 7;
        const int l  = cb >> 3;
        g_combo[cb * DD + d] =
            actor_w[(c >> 2) * DD + d] + street_w[(c & 3) * DD + d] + pos_w[l * DD + d];
    } else {
        const int idx  = bid - (64 + LL * 8);   // 0..511
        const int half = idx >> 8;
        const int q    = idx & 255;
        float acc = (half == 0) ? mlp_b[d] : 0.0f;
#pragma unroll
        for (int k = 0; k < 8; k++)
            if ((q >> k) & 1) acc += mlp_w[(half * 8 + k) * DD + d];
        g_H[(half * 256 + q) * DD + d] = acc;
    }
}

// ---------- K2: per-nibble sums/sumsqs + pairwise dot tables ----------
__global__ void precompute2()
{
    const int lane = threadIdx.x;
    const int bid  = blockIdx.x;
    const int d    = lane * 8;

    if (bid < 1536) {
        const int pair = bid >> 8;
        const int e    = bid & 255;
        const int qi   = e >> 4, qj = e & 15;
        const int pi[6] = {0, 0, 0, 1, 1, 2};
        const int pj[6] = {1, 2, 3, 2, 3, 3};
        const float* ti = g_T + (pi[pair] * 16 + qi) * DD + d;
        const float* tj = g_T + (pj[pair] * 16 + qj) * DD + d;
        const float4 a0 = *(const float4*)ti;
        const float4 a1 = *(const float4*)(ti + 4);
        const float4 b0 = *(const float4*)tj;
        const float4 b1 = *(const float4*)(tj + 4);
        float acc = a0.x*b0.x + a0.y*b0.y + a0.z*b0.z + a0.w*b0.w
                  + a1.x*b1.x + a1.y*b1.y + a1.z*b1.z + a1.w*b1.w;
#pragma unroll
        for (int o = 16; o > 0; o >>= 1)
            acc += __shfl_xor_sync(0xffffffffu, acc, o);
        if (lane == 0) g_D[pair * 256 + e] = acc;
    } else {
        const int s = bid - 1536;
        const float* t = g_T + s * DD + d;
        const float4 a0 = *(const float4*)t;
        const float4 a1 = *(const float4*)(t + 4);
        float sum = (a0.x + a0.y) + (a0.z + a0.w)
                  + (a1.x + a1.y) + (a1.z + a1.w);
        float sq  = a0.x*a0.x + a0.y*a0.y + a0.z*a0.z + a0.w*a0.w
                  + a1.x*a1.x + a1.y*a1.y + a1.z*a1.z + a1.w*a1.w;
#pragma unroll
        for (int o = 16; o > 0; o >>= 1) {
            sum += __shfl_xor_sync(0xffffffffu, sum, o);
            sq  += __shfl_xor_sync(0xffffffffu, sq,  o);
        }
        if (lane == 0) { g_S[s] = sum; g_Q[s] = sq; }
    }
}

// ---------- K3: LN stats per pattern ----------
__global__ void precompute3()
{
    const int p  = blockIdx.x * 256 + threadIdx.x;
    const int q0 = p & 15, q1 = (p >> 4) & 15, q2 = (p >> 8) & 15, q3 = p >> 12;
    const float sum = g_S[q0] + g_S[16 + q1] + g_S[32 + q2] + g_S[48 + q3];
    const float sq  = g_Q[q0] + g_Q[16 + q1] + g_Q[32 + q2] + g_Q[48 + q3]
        + 2.0f * ( g_D[0*256 + q0*16 + q1] + g_D[1*256 + q0*16 + q2]
                 + g_D[2*256 + q0*16 + q3] + g_D[3*256 + q1*16 + q2]
                 + g_D[4*256 + q1*16 + q3] + g_D[5*256 + q2*16 + q3]);
    const float mu  = sum * (1.0f / DD);
    const float var = fmaf(-mu, mu, sq * (1.0f / DD));
    float2 r; r.x = mu; r.y = rsqrtf(var + 1e-5f);
    g_stats[p] = r;
}

// ---------- K4: metadata pre-pass (pattern + ids packed per row) ----------
__global__ void prepass(const int*   __restrict__ token_ids,
                        const int*   __restrict__ actors,
                        const int*   __restrict__ streets,
                        const float* __restrict__ masks)
{
    const int b = blockIdx.x;            // 0..2047
    const int l = threadIdx.x;           // 0..127
    const long idc  = (long)b * SS + l;
    const float4* mp = (const float4*)(masks + idc * KK);
    const float4 m0 = __ldg(mp + 0);
    const float4 m1 = __ldg(mp + 1);
    const float4 m2 = __ldg(mp + 2);
    const float4 m3 = __ldg(mp + 3);

    unsigned pat = 0;
    pat |= (m0.x != 0.f) ? 1u       : 0u;
    pat |= (m0.y != 0.f) ? 1u <<  1 : 0u;
    pat |= (m0.z != 0.f) ? 1u <<  2 : 0u;
    pat |= (m0.w != 0.f) ? 1u <<  3 : 0u;
    pat |= (m1.x != 0.f) ? 1u <<  4 : 0u;
    pat |= (m1.y != 0.f) ? 1u <<  5 : 0u;
    pat |= (m1.z != 0.f) ? 1u <<  6 : 0u;
    pat |= (m1.w != 0.f) ? 1u <<  7 : 0u;
    pat |= (m2.x != 0.f) ? 1u <<  8 : 0u;
    pat |= (m2.y != 0.f) ? 1u <<  9 : 0u;
    pat |= (m2.z != 0.f) ? 1u << 10 : 0u;
    pat |= (m2.w != 0.f) ? 1u << 11 : 0u;
    pat |= (m3.x != 0.f) ? 1u << 12 : 0u;
    pat |= (m3.y != 0.f) ? 1u << 13 : 0u;
    pat |= (m3.z != 0.f) ? 1u << 14 : 0u;
    pat |= (m3.w != 0.f) ? 1u << 15 : 0u;

    const int tok = __ldg(token_ids + idc);
    const int a   = __ldg(actors    + idc);
    const int s   = __ldg(streets   + idc);

    unsigned meta = pat | ((unsigned)(a * 4 + s) << 16);
    if (tok >= 0) meta |= 1u << 31;
    g_meta[b * LL + l] = meta;
}

// ---------- main kernel ----------
__global__ __launch_bounds__(THREADS, 3)
void action_emb_kernel(const float* __restrict__ ln_g,
                       const float* __restrict__ ln_b,
                       float*       __restrict__ out)
{
    const int tid  = threadIdx.x;
    const int lane = tid & 31;
    const int warp = tid >> 5;
    const int d0   = lane * 8;

    const int l     = blockIdx.x & (LL - 1);
    const int chunk = blockIdx.x >> 7;
    const int b0    = chunk * B_PER_BLOCK + warp * ROWS_PER_WARP;

    const float4 gnA = *(const float4*)(ln_g + d0);
    const float4 gnB = *(const float4*)(ln_g + d0 + 4);
    const float4 bnA = *(const float4*)(ln_b + d0);
    const float4 bnB = *(const float4*)(ln_b + d0 + 4);
    const float* comboL = g_combo + (l * 8) * DD + d0;

    // each lane < 8 fetches one row's metadata
    unsigned m32 = 0;
    if (lane < ROWS_PER_WARP) m32 = g_meta[(b0 + lane) * LL + l];

    // prefetch row 0
    unsigned mc = __shfl_sync(0xffffffffu, m32, 0);
    float2   st = __ldg(&g_stats[mc & 0xFFFFu]);

    int oofs = (b0 * LL + l) * DD + d0;
    const int OSTEP = LL * DD;

#pragma unroll
    for (int it = 0; it < ROWS_PER_WARP; it++) {
        const unsigned pat = mc & 0xFFFFu;
        const float* H0 = g_H + ((pat & 255u)        ) * DD + d0;
        const float* H1 = g_H + ((pat >> 8) + 256u   ) * DD + d0;
        const float* cb = comboL + ((mc >> 16) & 7u) * DD;

        const float4 h0A = __ldg((const float4*)H0);
        const float4 h0B = __ldg((const float4*)(H0 + 4));
        const float4 h1A = __ldg((const float4*)H1);
        const float4 h1B = __ldg((const float4*)(H1 + 4));
        const float4 cA  = __ldg((const float4*)cb);
        const float4 cB  = __ldg((const float4*)(cb + 4));

        // prefetch next row's meta + stats
        const unsigned mn = __shfl_sync(0xffffffffu, m32, (it + 1) & 7);
        const float2   stN = __ldg(&g_stats[mn & 0xFFFFu]);

        const float rs   = st.y;
        const float nmrs = -st.x * rs;

        float4 oA, oB;
        oA.x = fmaxf(fmaf(fmaf(h0A.x + h1A.x, rs, nmrs), gnA.x, bnA.x), 0.0f) + cA.x;
        oA.y = fmaxf(fmaf(fmaf(h0A.y + h1A.y, rs, nmrs), gnA.y, bnA.y), 0.0f) + cA.y;
        oA.z = fmaxf(fmaf(fmaf(h0A.z + h1A.z, rs, nmrs), gnA.z, bnA.z), 0.0f) + cA.z;
        oA.w = fmaxf(fmaf(fmaf(h0A.w + h1A.w, rs, nmrs), gnA.w, bnA.w), 0.0f) + cA.w;
        oB.x = fmaxf(fmaf(fmaf(h0B.x + h1B.x, rs, nmrs), gnB.x, bnB.x), 0.0f) + cB.x;
        oB.y = fmaxf(fmaf(fmaf(h0B.y + h1B.y, rs, nmrs), gnB.y, bnB.y), 0.0f) + cB.y;
        oB.z = fmaxf(fmaf(fmaf(h0B.z + h1B.z, rs, nmrs), gnB.z, bnB.z), 0.0f) + cB.z;
        oB.w = fmaxf(fmaf(fmaf(h0B.w + h1B.w, rs, nmrs), gnB.w, bnB.w), 0.0f) + cB.w;

        if (!(mc >> 31)) {
            oA.x = oA.y = oA.z = oA.w = 0.0f;
            oB.x = oB.y = oB.z = oB.w = 0.0f;
        }

        *(float4*)(out + oofs)     = oA;
        *(float4*)(out + oofs + 4) = oB;
        oofs += OSTEP;
        mc = mn;
        st = stN;
    }
}

extern "C" void kernel_launch(void* const* d_in, const int* in_sizes, int n_in,
                              void* d_out, int out_size)
{
    const int*   token_ids = (const int*)  d_in[0];
    const int*   actors    = (const int*)  d_in[1];
    const int*   streets   = (const int*)  d_in[2];
    const float* masks     = (const float*)d_in[3];
    const float* actor_w   = (const float*)d_in[4];
    const float* street_w  = (const float*)d_in[5];
    const float* pos_w     = (const float*)d_in[6];
    const float* mlp_w     = (const float*)d_in[7];
    const float* mlp_b     = (const float*)d_in[8];
    const float* ln_g      = (const float*)d_in[9];
    const float* ln_b      = (const float*)d_in[10];
    float*       out       = (float*)d_out;

    precompute1<<<64 + LL * 8 + 512, 256>>>(mlp_w, mlp_b, actor_w, street_w, pos_w);
    precompute2<<<1600, 32>>>();
    precompute3<<<256, 256>>>();
    prepass<<<BB, LL>>>(token_ids, actors, streets, masks);
    action_emb_kernel<<<NBLOCKS, THREADS>>>(ln_g, ln_b, out);
}